// round 1
// baseline (speedup 1.0000x reference)
#include <cuda_runtime.h>

#define Bb 256
#define Tt 512
#define Vv 30000
#define Ee 256
#define Hh 32

// ---------------- static device scratch (no cudaMalloc allowed) ----------------
__device__ float g_embedW[(size_t)Vv * 192];       // 23 MB: [V][192] fwd gates 0..95, bwd 96..191 (bias folded)
__device__ float g_x1[(size_t)Bb * Tt * 64];       // 33.5 MB: layer0 outputs [B][T][64] (fwd 0..31, bwd 32..63)
__device__ float g_gi1[(size_t)Bb * Tt * 192];     // 100 MB: layer1 input gates [B][T][192]
__device__ float g_top[Bb * 64];                   // final hidden concat [B][64]
__device__ int   g_len[Bb];                        // per-batch valid length

// ---------------- lengths from attention mask (prefix mask) ----------------
__global__ void lens_kernel(const int* __restrict__ mask)
{
    int w = (blockIdx.x * blockDim.x + threadIdx.x) >> 5;
    int lane = threadIdx.x & 31;
    if (w >= Bb) return;
    int s = 0;
    for (int i = lane; i < Tt; i += 32) s += mask[w * Tt + i];
#pragma unroll
    for (int off = 16; off; off >>= 1) s += __shfl_xor_sync(0xffffffffu, s, off);
    if (lane == 0) g_len[w] = s;
}

// ---------------- C[M,192 (col_off..col_off+95)] = A[M,K] @ W[96,K]^T + bias ----------------
// BM=64, BN=96, BK=16, 128 threads, 8x6 microtile per thread.
// rowmask: if non-null and rowmask[m0]==0, whole block is padded rows -> dead, skip.
__global__ __launch_bounds__(128)
void gemm96_kernel(const float* __restrict__ A, const float* __restrict__ W,
                   const float* __restrict__ bias, float* __restrict__ C,
                   int M, int K, int col_off, const int* __restrict__ rowmask)
{
    const int BM = 64, BK = 16;
    __shared__ float As[BK][BM + 1];
    __shared__ float Bs[BK][96 + 1];

    int m0 = blockIdx.x * BM;
    if (rowmask && rowmask[m0] == 0) return;   // prefix-mask: first row padded => all padded

    int tid = threadIdx.x;
    int tx = tid & 15;        // 16 column groups * 6 cols
    int ty = tid >> 4;        // 8 row groups * 8 rows

    float acc[8][6];
#pragma unroll
    for (int i = 0; i < 8; i++)
#pragma unroll
        for (int j = 0; j < 6; j++) acc[i][j] = 0.f;

    for (int k0 = 0; k0 < K; k0 += BK) {
        // A tile 64x16
#pragma unroll
        for (int p = 0; p < 8; p++) {
            int kk = tid & 15;
            int m  = (tid >> 4) + p * 8;
            int gm = m0 + m;
            As[kk][m] = (gm < M) ? A[(size_t)gm * K + k0 + kk] : 0.f;
        }
        // B tile 96x16
#pragma unroll
        for (int p = 0; p < 12; p++) {
            int kk = tid & 15;
            int n  = (tid >> 4) + p * 8;
            Bs[kk][n] = W[(size_t)n * K + k0 + kk];
        }
        __syncthreads();
#pragma unroll
        for (int k = 0; k < BK; k++) {
            float a[8], b[6];
#pragma unroll
            for (int i = 0; i < 8; i++) a[i] = As[k][ty * 8 + i];
#pragma unroll
            for (int j = 0; j < 6; j++) b[j] = Bs[k][tx * 6 + j];
#pragma unroll
            for (int i = 0; i < 8; i++)
#pragma unroll
                for (int j = 0; j < 6; j++) acc[i][j] = fmaf(a[i], b[j], acc[i][j]);
        }
        __syncthreads();
    }
#pragma unroll
    for (int i = 0; i < 8; i++) {
        int gm = m0 + ty * 8 + i;
        if (gm >= M) continue;
#pragma unroll
        for (int j = 0; j < 6; j++) {
            int n = tx * 6 + j;
            C[(size_t)gm * 192 + col_off + n] = acc[i][j] + bias[n];
        }
    }
}

// ---------------- GRU step math (shared by both layers) ----------------
__device__ __forceinline__ float sigm(float x) { return 1.f / (1.f + __expf(-x)); }

// ---------------- layer 0 recurrence: warp = (batch, dir), gi from embedW gather ----------------
__global__ __launch_bounds__(128)
void gru_l0_kernel(const int* __restrict__ ids,
                   const float* __restrict__ Whh_f, const float* __restrict__ bhh_f,
                   const float* __restrict__ Whh_b, const float* __restrict__ bhh_b)
{
    int w = (blockIdx.x * blockDim.x + threadIdx.x) >> 5;
    int lane = threadIdx.x & 31;
    if (w >= 2 * Bb) return;
    int dir = w & 1;
    int b   = w >> 1;
    const float* Whh = dir ? Whh_b : Whh_f;
    const float* bhh = dir ? bhh_b : bhh_f;

    float Wr[32], Wz[32], Wn[32];
#pragma unroll
    for (int q = 0; q < 8; q++) {
        float4 v;
        v = *(const float4*)&Whh[(size_t)(lane) * 32 + q * 4];
        Wr[q*4] = v.x; Wr[q*4+1] = v.y; Wr[q*4+2] = v.z; Wr[q*4+3] = v.w;
        v = *(const float4*)&Whh[(size_t)(32 + lane) * 32 + q * 4];
        Wz[q*4] = v.x; Wz[q*4+1] = v.y; Wz[q*4+2] = v.z; Wz[q*4+3] = v.w;
        v = *(const float4*)&Whh[(size_t)(64 + lane) * 32 + q * 4];
        Wn[q*4] = v.x; Wn[q*4+1] = v.y; Wn[q*4+2] = v.z; Wn[q*4+3] = v.w;
    }
    float br = bhh[lane], bz = bhh[32 + lane], bn = bhh[64 + lane];

    int len = g_len[b];
    const int* idrow = ids + b * Tt;
    float h = 0.f;

    // prefetch gi for step 0
    int t0 = dir ? (len - 1) : 0;
    const float* gw = g_embedW + (size_t)idrow[t0] * 192 + dir * 96;
    float gir = gw[lane], giz = gw[32 + lane], gin = gw[64 + lane];

    for (int s = 0; s < len; s++) {
        int t = dir ? (len - 1 - s) : s;
        float cr = gir, cz = giz, cn = gin;
        if (s + 1 < len) {   // prefetch next step (independent of h)
            int tn = dir ? (len - 2 - s) : (s + 1);
            const float* gwn = g_embedW + (size_t)idrow[tn] * 192 + dir * 96;
            gir = gwn[lane]; giz = gwn[32 + lane]; gin = gwn[64 + lane];
        }
        float ar = br, az = bz, an = bn;
#pragma unroll
        for (int k = 0; k < 32; k++) {
            float hk = __shfl_sync(0xffffffffu, h, k);
            ar = fmaf(Wr[k], hk, ar);
            az = fmaf(Wz[k], hk, az);
            an = fmaf(Wn[k], hk, an);
        }
        float r = sigm(cr + ar);
        float z = sigm(cz + az);
        float n = tanhf(fmaf(r, an, cn));
        h = fmaf(z, h - n, n);                       // (1-z)*n + z*h
        g_x1[((size_t)b * Tt + t) * 64 + dir * 32 + lane] = h;
    }
    // padded region of g_x1 is dead downstream (layer1 freezes there) -> no store needed
}

// ---------------- layer 1 recurrence: gi from precomputed g_gi1, only final h kept ----------------
__global__ __launch_bounds__(128)
void gru_l1_kernel(const float* __restrict__ Whh_f, const float* __restrict__ bhh_f,
                   const float* __restrict__ Whh_b, const float* __restrict__ bhh_b)
{
    int w = (blockIdx.x * blockDim.x + threadIdx.x) >> 5;
    int lane = threadIdx.x & 31;
    if (w >= 2 * Bb) return;
    int dir = w & 1;
    int b   = w >> 1;
    const float* Whh = dir ? Whh_b : Whh_f;
    const float* bhh = dir ? bhh_b : bhh_f;

    float Wr[32], Wz[32], Wn[32];
#pragma unroll
    for (int q = 0; q < 8; q++) {
        float4 v;
        v = *(const float4*)&Whh[(size_t)(lane) * 32 + q * 4];
        Wr[q*4] = v.x; Wr[q*4+1] = v.y; Wr[q*4+2] = v.z; Wr[q*4+3] = v.w;
        v = *(const float4*)&Whh[(size_t)(32 + lane) * 32 + q * 4];
        Wz[q*4] = v.x; Wz[q*4+1] = v.y; Wz[q*4+2] = v.z; Wz[q*4+3] = v.w;
        v = *(const float4*)&Whh[(size_t)(64 + lane) * 32 + q * 4];
        Wn[q*4] = v.x; Wn[q*4+1] = v.y; Wn[q*4+2] = v.z; Wn[q*4+3] = v.w;
    }
    float br = bhh[lane], bz = bhh[32 + lane], bn = bhh[64 + lane];

    int len = g_len[b];
    float h = 0.f;

    int t0 = dir ? (len - 1) : 0;
    const float* gw = g_gi1 + ((size_t)b * Tt + t0) * 192 + dir * 96;
    float gir = gw[lane], giz = gw[32 + lane], gin = gw[64 + lane];

    for (int s = 0; s < len; s++) {
        float cr = gir, cz = giz, cn = gin;
        if (s + 1 < len) {
            int tn = dir ? (len - 2 - s) : (s + 1);
            const float* gwn = g_gi1 + ((size_t)b * Tt + tn) * 192 + dir * 96;
            gir = gwn[lane]; giz = gwn[32 + lane]; gin = gwn[64 + lane];
        }
        float ar = br, az = bz, an = bn;
#pragma unroll
        for (int k = 0; k < 32; k++) {
            float hk = __shfl_sync(0xffffffffu, h, k);
            ar = fmaf(Wr[k], hk, ar);
            az = fmaf(Wz[k], hk, az);
            an = fmaf(Wn[k], hk, an);
        }
        float r = sigm(cr + ar);
        float z = sigm(cz + az);
        float n = tanhf(fmaf(r, an, cn));
        h = fmaf(z, h - n, n);
    }
    g_top[b * 64 + dir * 32 + lane] = h;
}

// ---------------- final linear [B,64] @ [6,64]^T + bias ----------------
__global__ void out_kernel(const float* __restrict__ Wout, const float* __restrict__ bout,
                           float* __restrict__ out)
{
    int w = (blockIdx.x * blockDim.x + threadIdx.x) >> 5;
    int lane = threadIdx.x & 31;
    if (w >= Bb) return;
    float t0 = g_top[w * 64 + lane];
    float t1 = g_top[w * 64 + 32 + lane];
#pragma unroll
    for (int o = 0; o < 6; o++) {
        float s = t0 * Wout[o * 64 + lane] + t1 * Wout[o * 64 + 32 + lane];
#pragma unroll
        for (int off = 16; off; off >>= 1) s += __shfl_xor_sync(0xffffffffu, s, off);
        if (lane == 0) out[w * 6 + o] = s + bout[o];
    }
}

// ---------------- launch ----------------
extern "C" void kernel_launch(void* const* d_in, const int* in_sizes, int n_in,
                              void* d_out, int out_size)
{
    const int*   ids     = (const int*)d_in[0];
    const int*   mask    = (const int*)d_in[1];
    const float* embed   = (const float*)d_in[2];
    const float* Wih_l0f = (const float*)d_in[3];
    const float* Whh_l0f = (const float*)d_in[4];
    const float* bih_l0f = (const float*)d_in[5];
    const float* bhh_l0f = (const float*)d_in[6];
    const float* Wih_l0b = (const float*)d_in[7];
    const float* Whh_l0b = (const float*)d_in[8];
    const float* bih_l0b = (const float*)d_in[9];
    const float* bhh_l0b = (const float*)d_in[10];
    const float* Wih_l1f = (const float*)d_in[11];
    const float* Whh_l1f = (const float*)d_in[12];
    const float* bih_l1f = (const float*)d_in[13];
    const float* bhh_l1f = (const float*)d_in[14];
    const float* Wih_l1b = (const float*)d_in[15];
    const float* Whh_l1b = (const float*)d_in[16];
    const float* bih_l1b = (const float*)d_in[17];
    const float* bhh_l1b = (const float*)d_in[18];
    const float* Wout    = (const float*)d_in[19];
    const float* bout    = (const float*)d_in[20];
    float* out = (float*)d_out;

    float *p_embedW = nullptr, *p_x1 = nullptr, *p_gi1 = nullptr;
    cudaGetSymbolAddress((void**)&p_embedW, g_embedW);
    cudaGetSymbolAddress((void**)&p_x1, g_x1);
    cudaGetSymbolAddress((void**)&p_gi1, g_gi1);

    // 1) lengths
    lens_kernel<<<8, 1024>>>(mask);
    // 2) embedW = embed @ [Wih_l0f;Wih_l0b]^T + bias   (fold embedding into gate table)
    gemm96_kernel<<<(Vv + 63) / 64, 128>>>(embed, Wih_l0f, bih_l0f, p_embedW, Vv, Ee, 0,  nullptr);
    gemm96_kernel<<<(Vv + 63) / 64, 128>>>(embed, Wih_l0b, bih_l0b, p_embedW, Vv, Ee, 96, nullptr);
    // 3) layer-0 bidirectional recurrence -> x1
    gru_l0_kernel<<<128, 128>>>(ids, Whh_l0f, bhh_l0f, Whh_l0b, bhh_l0b);
    // 4) gi1 = x1 @ Wih_l1^T + bias (masked blocks skipped)
    gemm96_kernel<<<(Bb * Tt) / 64, 128>>>(p_x1, Wih_l1f, bih_l1f, p_gi1, Bb * Tt, 64, 0,  mask);
    gemm96_kernel<<<(Bb * Tt) / 64, 128>>>(p_x1, Wih_l1b, bih_l1b, p_gi1, Bb * Tt, 64, 96, mask);
    // 5) layer-1 recurrence -> final hiddens
    gru_l1_kernel<<<128, 128>>>(Whh_l1f, bhh_l1f, Whh_l1b, bhh_l1b);
    // 6) output projection
    out_kernel<<<8, 1024>>>(Wout, bout, out);
}

// round 2
// speedup vs baseline: 1.4708x; 1.4708x over previous
#include <cuda_runtime.h>

#define Bb 256
#define Tt 512
#define Vv 30000
#define Ee 256
#define Hh 32

// ---------------- static device scratch ----------------
__device__ float g_embedW[(size_t)Vv * 192];       // [V][192]: fwd gates 0..95, bwd 96..191 (bih folded)
__device__ float g_x1[(size_t)Bb * Tt * 64];       // layer0 outputs [B][T][64]
__device__ float g_gi1[(size_t)Bb * Tt * 192];     // layer1 input gates [B][T][192]
__device__ float g_top[Bb * 64];                   // final hidden concat [B][64]
__device__ int   g_len[Bb];

// ---------------- fast math ----------------
__device__ __forceinline__ float fast_exp(float x) {
    float y; asm("ex2.approx.f32 %0, %1;" : "=f"(y) : "f"(x * 1.4426950408889634f));
    return y;
}
__device__ __forceinline__ float fast_rcp(float x) {
    float y; asm("rcp.approx.f32 %0, %1;" : "=f"(y) : "f"(x));
    return y;
}
__device__ __forceinline__ float fast_sigm(float x) { return fast_rcp(1.f + fast_exp(-x)); }
__device__ __forceinline__ float fast_tanh(float x) { return 1.f - 2.f * fast_rcp(1.f + fast_exp(2.f * x)); }

// packed fp32x2 fma (Blackwell FFMA2 — 2x fp32 rate)
__device__ __forceinline__ void fma2(unsigned long long& d, unsigned long long a, unsigned long long b) {
    asm("fma.rn.f32x2 %0, %1, %2, %0;" : "+l"(d) : "l"(a), "l"(b));
}
__device__ __forceinline__ unsigned long long dup2(float v) {
    unsigned long long r; asm("mov.b64 %0, {%1, %1};" : "=l"(r) : "f"(v));
    return r;
}

// ---------------- lengths from attention mask (prefix mask) ----------------
__global__ void lens_kernel(const int* __restrict__ mask)
{
    int w = (blockIdx.x * blockDim.x + threadIdx.x) >> 5;
    int lane = threadIdx.x & 31;
    if (w >= Bb) return;
    int s = 0;
    for (int i = lane; i < Tt; i += 32) s += mask[w * Tt + i];
#pragma unroll
    for (int off = 16; off; off >>= 1) s += __shfl_xor_sync(0xffffffffu, s, off);
    if (lane == 0) g_len[w] = s;
}

// ---------------- fused GEMM: C[M,192] = A[M,K] @ [Wf;Wb][192,K]^T + [bf;bb] ----------------
// BM=64, BN=192, BK=16, 256 threads. Microtile 8 rows (as 4 f32x2 pairs) x 6 cols (tx + 32j).
__global__ __launch_bounds__(256)
void gemm192_kernel(const float* __restrict__ A,
                    const float* __restrict__ Wf, const float* __restrict__ Wb,
                    const float* __restrict__ bf, const float* __restrict__ bb_,
                    float* __restrict__ C, int M, int K,
                    const int* __restrict__ rowmask)
{
    __shared__ float As[16][68];
    __shared__ float Bs[16][196];

    int m0 = blockIdx.x * 64;
    if (rowmask && rowmask[m0] == 0) return;   // prefix mask: whole block padded

    int tid = threadIdx.x;
    int tx = tid & 31;        // col base: cols tx + 32*j, j=0..5
    int ty = tid >> 5;        // row base: rows ty*8 .. ty*8+7

    unsigned long long acc[4][6];
#pragma unroll
    for (int i = 0; i < 4; i++)
#pragma unroll
        for (int j = 0; j < 6; j++) acc[i][j] = 0ull;

    int lkk = tid & 15;
    int lrow = tid >> 4;      // 0..15

    for (int k0 = 0; k0 < K; k0 += 16) {
        // A tile 64x16: 4 elements/thread
#pragma unroll
        for (int p = 0; p < 4; p++) {
            int m = lrow + p * 16;
            int gm = m0 + m;
            As[lkk][m] = (gm < M) ? A[(size_t)gm * K + k0 + lkk] : 0.f;
        }
        // B tile 192x16: 12 elements/thread; rows 0..95 from Wf, 96..191 from Wb
#pragma unroll
        for (int p = 0; p < 12; p++) {
            int n = lrow + p * 16;
            const float* Wsrc = (n < 96) ? (Wf + (size_t)n * K) : (Wb + (size_t)(n - 96) * K);
            Bs[lkk][n] = Wsrc[k0 + lkk];
        }
        __syncthreads();
#pragma unroll
        for (int k = 0; k < 16; k++) {
            unsigned long long a2[4];
#pragma unroll
            for (int i = 0; i < 4; i++)
                a2[i] = *(const unsigned long long*)&As[k][ty * 8 + 2 * i];
            unsigned long long b2[6];
#pragma unroll
            for (int j = 0; j < 6; j++)
                b2[j] = dup2(Bs[k][tx + 32 * j]);
#pragma unroll
            for (int i = 0; i < 4; i++)
#pragma unroll
                for (int j = 0; j < 6; j++)
                    fma2(acc[i][j], a2[i], b2[j]);
        }
        __syncthreads();
    }

#pragma unroll
    for (int i = 0; i < 4; i++) {
        int gm0 = m0 + ty * 8 + 2 * i;
#pragma unroll
        for (int j = 0; j < 6; j++) {
            int n = tx + 32 * j;
            float bias = (n < 96) ? bf[n] : bb_[n - 96];
            float lo = __uint_as_float((unsigned)(acc[i][j] & 0xffffffffull));
            float hi = __uint_as_float((unsigned)(acc[i][j] >> 32));
            if (gm0 < M)     C[(size_t)gm0 * 192 + n]       = lo + bias;
            if (gm0 + 1 < M) C[(size_t)(gm0 + 1) * 192 + n] = hi + bias;
        }
    }
}

// ---------------- GRU recurrence: warp = (batch, dir) ----------------
// L0: gi gathered from g_embedW via token ids; writes every h to g_x1.
// L1: gi read from g_gi1; writes only final h to g_top.
template<bool L0>
__global__ __launch_bounds__(128)
void gru_kernel(const float* __restrict__ gi,
                const int* __restrict__ ids,
                const float* __restrict__ Whh_f, const float* __restrict__ bhh_f,
                const float* __restrict__ Whh_b, const float* __restrict__ bhh_b)
{
    __shared__ int sid[4][Tt];
    int wib = threadIdx.x >> 5;
    int w = blockIdx.x * 4 + wib;
    int lane = threadIdx.x & 31;
    if (w >= 2 * Bb) return;
    int dir = w & 1;
    int b   = w >> 1;
    const float* Whh = dir ? Whh_b : Whh_f;
    const float* bhh = dir ? bhh_b : bhh_f;

    float Wr[32], Wz[32], Wn[32];
#pragma unroll
    for (int q = 0; q < 8; q++) {
        float4 v;
        v = *(const float4*)&Whh[(size_t)lane * 32 + q * 4];
        Wr[q*4] = v.x; Wr[q*4+1] = v.y; Wr[q*4+2] = v.z; Wr[q*4+3] = v.w;
        v = *(const float4*)&Whh[(size_t)(32 + lane) * 32 + q * 4];
        Wz[q*4] = v.x; Wz[q*4+1] = v.y; Wz[q*4+2] = v.z; Wz[q*4+3] = v.w;
        v = *(const float4*)&Whh[(size_t)(64 + lane) * 32 + q * 4];
        Wn[q*4] = v.x; Wn[q*4+1] = v.y; Wn[q*4+2] = v.z; Wn[q*4+3] = v.w;
    }
    float br = bhh[lane], bz = bhh[32 + lane], bn = bhh[64 + lane];

    int len = g_len[b];

    if (L0) {
        const int* idrow = ids + b * Tt;
        for (int i = lane; i < len; i += 32) sid[wib][i] = idrow[i];
        __syncwarp();
    }

    int tstep = dir ? -1 : 1;
    int tcur  = dir ? (len - 1) : 0;

    // gi row pointer for logical time t
    auto gip = [&](int t) -> const float* {
        if (L0) return gi + (size_t)sid[wib][t] * 192 + dir * 96;
        else    return gi + ((size_t)b * Tt + t) * 192 + dir * 96;
    };

    // distance-2 prefetch pipeline
    const float* p0 = gip(tcur);
    float g0r = __ldg(p0 + lane), g0z = __ldg(p0 + 32 + lane), g0n = __ldg(p0 + 64 + lane);
    float g1r = g0r, g1z = g0z, g1n = g0n;
    if (len > 1) {
        const float* p1 = gip(tcur + tstep);
        g1r = __ldg(p1 + lane); g1z = __ldg(p1 + 32 + lane); g1n = __ldg(p1 + 64 + lane);
    }

    float h = 0.f;
    for (int s = 0; s < len; s++) {
        float cr = g0r, cz = g0z, cn = g0n;
        g0r = g1r; g0z = g1z; g0n = g1n;
        if (s + 2 < len) {
            const float* p = gip(tcur + 2 * tstep);
            g1r = __ldg(p + lane); g1z = __ldg(p + 32 + lane); g1n = __ldg(p + 64 + lane);
        }

        // 96-wide matvec via shfl broadcast, 4-way split accumulators
        float ar0 = 0.f, ar1 = 0.f, ar2 = 0.f, ar3 = 0.f;
        float az0 = 0.f, az1 = 0.f, az2 = 0.f, az3 = 0.f;
        float an0 = 0.f, an1 = 0.f, an2 = 0.f, an3 = 0.f;
#pragma unroll
        for (int k = 0; k < 32; k += 4) {
            float h0 = __shfl_sync(0xffffffffu, h, k);
            float h1 = __shfl_sync(0xffffffffu, h, k + 1);
            float h2 = __shfl_sync(0xffffffffu, h, k + 2);
            float h3 = __shfl_sync(0xffffffffu, h, k + 3);
            ar0 = fmaf(Wr[k],     h0, ar0);
            ar1 = fmaf(Wr[k + 1], h1, ar1);
            ar2 = fmaf(Wr[k + 2], h2, ar2);
            ar3 = fmaf(Wr[k + 3], h3, ar3);
            az0 = fmaf(Wz[k],     h0, az0);
            az1 = fmaf(Wz[k + 1], h1, az1);
            az2 = fmaf(Wz[k + 2], h2, az2);
            az3 = fmaf(Wz[k + 3], h3, az3);
            an0 = fmaf(Wn[k],     h0, an0);
            an1 = fmaf(Wn[k + 1], h1, an1);
            an2 = fmaf(Wn[k + 2], h2, an2);
            an3 = fmaf(Wn[k + 3], h3, an3);
        }
        float ar = ((ar0 + ar1) + (ar2 + ar3)) + br;
        float az = ((az0 + az1) + (az2 + az3)) + bz;
        float an = ((an0 + an1) + (an2 + an3)) + bn;

        float r = fast_sigm(cr + ar);
        float z = fast_sigm(cz + az);
        float n = fast_tanh(fmaf(r, an, cn));
        h = fmaf(z, h - n, n);                    // (1-z)*n + z*h

        if (L0)
            g_x1[((size_t)b * Tt + tcur) * 64 + dir * 32 + lane] = h;
        tcur += tstep;
    }
    if (!L0)
        g_top[b * 64 + dir * 32 + lane] = h;
}

// ---------------- final linear [B,64] @ [6,64]^T + bias ----------------
__global__ void out_kernel(const float* __restrict__ Wout, const float* __restrict__ bout,
                           float* __restrict__ out)
{
    int w = (blockIdx.x * blockDim.x + threadIdx.x) >> 5;
    int lane = threadIdx.x & 31;
    if (w >= Bb) return;
    float t0 = g_top[w * 64 + lane];
    float t1 = g_top[w * 64 + 32 + lane];
#pragma unroll
    for (int o = 0; o < 6; o++) {
        float s = t0 * Wout[o * 64 + lane] + t1 * Wout[o * 64 + 32 + lane];
#pragma unroll
        for (int off = 16; off; off >>= 1) s += __shfl_xor_sync(0xffffffffu, s, off);
        if (lane == 0) out[w * 6 + o] = s + bout[o];
    }
}

// ---------------- launch ----------------
extern "C" void kernel_launch(void* const* d_in, const int* in_sizes, int n_in,
                              void* d_out, int out_size)
{
    const int*   ids     = (const int*)d_in[0];
    const int*   mask    = (const int*)d_in[1];
    const float* embed   = (const float*)d_in[2];
    const float* Wih_l0f = (const float*)d_in[3];
    const float* Whh_l0f = (const float*)d_in[4];
    const float* bih_l0f = (const float*)d_in[5];
    const float* bhh_l0f = (const float*)d_in[6];
    const float* Wih_l0b = (const float*)d_in[7];
    const float* Whh_l0b = (const float*)d_in[8];
    const float* bih_l0b = (const float*)d_in[9];
    const float* bhh_l0b = (const float*)d_in[10];
    const float* Wih_l1f = (const float*)d_in[11];
    const float* Whh_l1f = (const float*)d_in[12];
    const float* bih_l1f = (const float*)d_in[13];
    const float* bhh_l1f = (const float*)d_in[14];
    const float* Wih_l1b = (const float*)d_in[15];
    const float* Whh_l1b = (const float*)d_in[16];
    const float* bih_l1b = (const float*)d_in[17];
    const float* bhh_l1b = (const float*)d_in[18];
    const float* Wout    = (const float*)d_in[19];
    const float* bout    = (const float*)d_in[20];
    float* out = (float*)d_out;

    float *p_embedW = nullptr, *p_x1 = nullptr, *p_gi1 = nullptr;
    cudaGetSymbolAddress((void**)&p_embedW, g_embedW);
    cudaGetSymbolAddress((void**)&p_x1, g_x1);
    cudaGetSymbolAddress((void**)&p_gi1, g_gi1);

    // 1) lengths
    lens_kernel<<<8, 1024>>>(mask);
    // 2) embedW = embed @ [Wih_l0f;Wih_l0b]^T + bias (fused fwd+bwd)
    gemm192_kernel<<<(Vv + 63) / 64, 256>>>(embed, Wih_l0f, Wih_l0b, bih_l0f, bih_l0b,
                                            p_embedW, Vv, Ee, nullptr);
    // 3) layer-0 bidirectional recurrence -> x1
    gru_kernel<true><<<128, 128>>>(p_embedW, ids, Whh_l0f, bhh_l0f, Whh_l0b, bhh_l0b);
    // 4) gi1 = x1 @ [Wih_l1f;Wih_l1b]^T + bias (masked blocks skipped)
    gemm192_kernel<<<(Bb * Tt) / 64, 256>>>(p_x1, Wih_l1f, Wih_l1b, bih_l1f, bih_l1b,
                                            p_gi1, Bb * Tt, 64, mask);
    // 5) layer-1 recurrence -> final hiddens
    gru_kernel<false><<<128, 128>>>(p_gi1, nullptr, Whh_l1f, bhh_l1f, Whh_l1b, bhh_l1b);
    // 6) output projection
    out_kernel<<<8, 1024>>>(Wout, bout, out);
}

// round 3
// speedup vs baseline: 1.4898x; 1.0129x over previous
#include <cuda_runtime.h>

typedef unsigned long long ull;

#define Bb 256
#define Tt 512
#define Vv 30000
#define Ee 256

// ---------------- static device scratch ----------------
__device__ float g_embedW[(size_t)Vv * 192];       // [V][192] fwd gates 0..95, bwd 96..191 (bih folded)
__device__ float g_x1[(size_t)Bb * Tt * 64];       // layer0 outputs [B][T][64]
__device__ float g_gi1[(size_t)Bb * Tt * 192];     // layer1 input gates [B][T][192]
__device__ float g_top[Bb * 64];
__device__ int   g_len[Bb];

// ---------------- fast math ----------------
__device__ __forceinline__ float fast_exp(float x) {
    float y; asm("ex2.approx.f32 %0, %1;" : "=f"(y) : "f"(x * 1.4426950408889634f));
    return y;
}
__device__ __forceinline__ float fast_rcp(float x) {
    float y; asm("rcp.approx.f32 %0, %1;" : "=f"(y) : "f"(x));
    return y;
}
__device__ __forceinline__ float fast_sigm(float x) { return fast_rcp(1.f + fast_exp(-x)); }
__device__ __forceinline__ float fast_tanh(float x) { return 1.f - 2.f * fast_rcp(1.f + fast_exp(2.f * x)); }

// packed fp32x2 ops
__device__ __forceinline__ void fma2(ull& d, ull a, ull b) {
    asm("fma.rn.f32x2 %0, %1, %2, %0;" : "+l"(d) : "l"(a), "l"(b));
}
__device__ __forceinline__ ull add2(ull a, ull b) {
    ull r; asm("add.rn.f32x2 %0, %1, %2;" : "=l"(r) : "l"(a), "l"(b));
    return r;
}
__device__ __forceinline__ ull dup2(float v) {
    ull r; asm("mov.b64 %0, {%1, %1};" : "=l"(r) : "f"(v));
    return r;
}
__device__ __forceinline__ float hsum2(ull v) {
    unsigned lo, hi;
    asm("mov.b64 {%0, %1}, %2;" : "=r"(lo), "=r"(hi) : "l"(v));
    return __uint_as_float(lo) + __uint_as_float(hi);
}

// ---------------- lengths from attention mask (prefix mask) ----------------
__global__ void lens_kernel(const int* __restrict__ mask)
{
    int w = (blockIdx.x * blockDim.x + threadIdx.x) >> 5;
    int lane = threadIdx.x & 31;
    if (w >= Bb) return;
    int s = 0;
    for (int i = lane; i < Tt; i += 32) s += mask[w * Tt + i];
#pragma unroll
    for (int off = 16; off; off >>= 1) s += __shfl_xor_sync(0xffffffffu, s, off);
    if (lane == 0) g_len[w] = s;
}

// ---------------- fused GEMM: C[M,192] = A[M,K] @ [Wf;Wb][192,K]^T + [bf;bb] ----------------
// BM=64, BN=192, BK=16, 256 threads, double-buffered smem, B stored as dup'd f32x2.
#define AS_PAD 68
#define BS_PAD 194
#define GEMM_SMEM (2 * 16 * AS_PAD * 4 + 2 * 16 * BS_PAD * 8)

extern __shared__ char dynsmem[];

__global__ __launch_bounds__(256, 2)
void gemm192_kernel(const float* __restrict__ A,
                    const float* __restrict__ Wf, const float* __restrict__ Wb,
                    const float* __restrict__ bf, const float* __restrict__ bb_,
                    float* __restrict__ C, int M, int K,
                    const int* __restrict__ rowmask)
{
    float (*As)[16][AS_PAD] = (float (*)[16][AS_PAD])dynsmem;
    ull   (*Bs)[16][BS_PAD] = (ull (*)[16][BS_PAD])(dynsmem + 2 * 16 * AS_PAD * 4);

    int m0 = blockIdx.x * 64;
    if (rowmask && rowmask[m0] == 0) return;   // prefix mask: whole 64-row block padded

    int tid = threadIdx.x;
    int tx = tid & 31;        // cols tx + 32*j, j=0..5
    int ty = tid >> 5;        // rows ty*8 .. ty*8+7
    int lkk = tid & 15;
    int lrow = tid >> 4;

    // global pointers for tile loading
    const float* aptr[4]; bool av[4];
#pragma unroll
    for (int p = 0; p < 4; p++) {
        int gm = m0 + lrow + 16 * p;
        av[p] = gm < M;
        aptr[p] = A + (size_t)(av[p] ? gm : 0) * K + lkk;
    }
    const float* bptr[12];
#pragma unroll
    for (int p = 0; p < 12; p++) {
        int n = lrow + 16 * p;
        bptr[p] = ((n < 96) ? Wf + (size_t)n * K : Wb + (size_t)(n - 96) * K) + lkk;
    }

    ull acc[4][6];
#pragma unroll
    for (int i = 0; i < 4; i++)
#pragma unroll
        for (int j = 0; j < 6; j++) acc[i][j] = 0ull;

    // preload tile 0
#pragma unroll
    for (int p = 0; p < 4; p++)
        As[0][lkk][lrow + 16 * p] = av[p] ? aptr[p][0] : 0.f;
#pragma unroll
    for (int p = 0; p < 12; p++)
        Bs[0][lkk][lrow + 16 * p] = dup2(bptr[p][0]);
    __syncthreads();

    int kiter = K >> 4;
    int buf = 0;
    for (int it = 0; it < kiter; ++it) {
        bool more = (it + 1) < kiter;
        float pa[4]; ull pb[12];
        if (more) {
            int off = (it + 1) << 4;
#pragma unroll
            for (int p = 0; p < 4; p++) pa[p] = av[p] ? aptr[p][off] : 0.f;
#pragma unroll
            for (int p = 0; p < 12; p++) pb[p] = dup2(bptr[p][off]);
        }
#pragma unroll
        for (int k = 0; k < 16; k++) {
            ulonglong2 q0 = *(const ulonglong2*)&As[buf][k][ty * 8];
            ulonglong2 q1 = *(const ulonglong2*)&As[buf][k][ty * 8 + 4];
            ull a2[4] = { q0.x, q0.y, q1.x, q1.y };
            ull b2[6];
#pragma unroll
            for (int j = 0; j < 6; j++) b2[j] = Bs[buf][k][tx + 32 * j];
#pragma unroll
            for (int i = 0; i < 4; i++)
#pragma unroll
                for (int j = 0; j < 6; j++)
                    fma2(acc[i][j], a2[i], b2[j]);
        }
        if (!more) break;
        int nb = buf ^ 1;
#pragma unroll
        for (int p = 0; p < 4; p++)  As[nb][lkk][lrow + 16 * p] = pa[p];
#pragma unroll
        for (int p = 0; p < 12; p++) Bs[nb][lkk][lrow + 16 * p] = pb[p];
        __syncthreads();
        buf = nb;
    }

#pragma unroll
    for (int i = 0; i < 4; i++) {
        int gm0 = m0 + ty * 8 + 2 * i;
#pragma unroll
        for (int j = 0; j < 6; j++) {
            int n = tx + 32 * j;
            float bias = (n < 96) ? bf[n] : bb_[n - 96];
            unsigned lo, hi;
            asm("mov.b64 {%0, %1}, %2;" : "=r"(lo), "=r"(hi) : "l"(acc[i][j]));
            if (gm0 < M)     C[(size_t)gm0 * 192 + n]       = __uint_as_float(lo) + bias;
            if (gm0 + 1 < M) C[(size_t)(gm0 + 1) * 192 + n] = __uint_as_float(hi) + bias;
        }
    }
}

// ---------------- GRU recurrence: warp = (batch, dir) ----------------
// matvec done in f32x2: h broadcast via smem (parity-double-buffered), 48 FFMA2/step.
template<bool L0>
__global__ __launch_bounds__(128)
void gru_kernel(const float* __restrict__ gi,
                const int* __restrict__ ids,
                const float* __restrict__ Whh_f, const float* __restrict__ bhh_f,
                const float* __restrict__ Whh_b, const float* __restrict__ bhh_b)
{
    __shared__ float sh[4][2][32];        // [warp][parity][lane]
    __shared__ int   sid[4][Tt];          // used by L0 only

    int wib = threadIdx.x >> 5;
    int lane = threadIdx.x & 31;
    int w = blockIdx.x * 4 + wib;
    int dir = w & 1;
    int b   = w >> 1;
    const float* Whh = dir ? Whh_b : Whh_f;
    const float* bhh = dir ? bhh_b : bhh_f;

    // pack Whh rows into f32x2 pairs (lane owns rows lane, 32+lane, 64+lane)
    ull Wr2[16], Wz2[16], Wn2[16];
#pragma unroll
    for (int q = 0; q < 8; q++) {
        float4 v;
        v = *(const float4*)&Whh[(size_t)lane * 32 + q * 4];
        Wr2[2*q]   = dup2(0.f); // placeholder to keep compiler happy, overwritten below
        asm("mov.b64 %0, {%1, %2};" : "=l"(Wr2[2*q])   : "f"(v.x), "f"(v.y));
        asm("mov.b64 %0, {%1, %2};" : "=l"(Wr2[2*q+1]) : "f"(v.z), "f"(v.w));
        v = *(const float4*)&Whh[(size_t)(32 + lane) * 32 + q * 4];
        asm("mov.b64 %0, {%1, %2};" : "=l"(Wz2[2*q])   : "f"(v.x), "f"(v.y));
        asm("mov.b64 %0, {%1, %2};" : "=l"(Wz2[2*q+1]) : "f"(v.z), "f"(v.w));
        v = *(const float4*)&Whh[(size_t)(64 + lane) * 32 + q * 4];
        asm("mov.b64 %0, {%1, %2};" : "=l"(Wn2[2*q])   : "f"(v.x), "f"(v.y));
        asm("mov.b64 %0, {%1, %2};" : "=l"(Wn2[2*q+1]) : "f"(v.z), "f"(v.w));
    }
    float br = bhh[lane], bz = bhh[32 + lane], bn = bhh[64 + lane];

    int len = g_len[b];

    if (L0) {
        const int* idrow = ids + b * Tt;
        for (int i = lane; i < len; i += 32) sid[wib][i] = idrow[i];
        __syncwarp();
    }

    int tstep = dir ? -1 : 1;
    int tcur  = dir ? (len - 1) : 0;

    auto gip = [&](int t) -> const float* {
        if (L0) return gi + (size_t)sid[wib][t] * 192 + dir * 96;
        else    return gi + ((size_t)b * Tt + t) * 192 + dir * 96;
    };

    // distance-2 prefetch
    const float* p0 = gip(tcur);
    float g0r = __ldg(p0 + lane), g0z = __ldg(p0 + 32 + lane), g0n = __ldg(p0 + 64 + lane);
    float g1r = g0r, g1z = g0z, g1n = g0n;
    if (len > 1) {
        const float* p1 = gip(tcur + tstep);
        g1r = __ldg(p1 + lane); g1z = __ldg(p1 + 32 + lane); g1n = __ldg(p1 + 64 + lane);
    }

    float h = 0.f;
    float* outp = L0 ? (g_x1 + ((size_t)b * Tt + tcur) * 64 + dir * 32 + lane) : nullptr;
    long outstep = (long)tstep * 64;

    for (int s = 0; s < len; s++) {
        float cr = g0r, cz = g0z, cn = g0n;
        g0r = g1r; g0z = g1z; g0n = g1n;
        if (s + 2 < len) {
            const float* p = gip(tcur + 2 * tstep);
            g1r = __ldg(p + lane); g1z = __ldg(p + 32 + lane); g1n = __ldg(p + 64 + lane);
        }

        // broadcast h via parity-buffered smem
        int par = s & 1;
        sh[wib][par][lane] = h;
        __syncwarp();
        ull h2[16];
#pragma unroll
        for (int i = 0; i < 8; i++) {
            ulonglong2 p2 = *(const ulonglong2*)&sh[wib][par][4 * i];
            h2[2 * i] = p2.x; h2[2 * i + 1] = p2.y;
        }

        ull ra = 0ull, rb = 0ull, za = 0ull, zb = 0ull, na = 0ull, nb2 = 0ull;
#pragma unroll
        for (int k = 0; k < 16; k += 2) {
            fma2(ra, Wr2[k],     h2[k]);
            fma2(rb, Wr2[k + 1], h2[k + 1]);
            fma2(za, Wz2[k],     h2[k]);
            fma2(zb, Wz2[k + 1], h2[k + 1]);
            fma2(na, Wn2[k],     h2[k]);
            fma2(nb2, Wn2[k + 1], h2[k + 1]);
        }
        float ar = hsum2(add2(ra, rb));
        float az = hsum2(add2(za, zb));
        float an = hsum2(add2(na, nb2));

        float r = fast_sigm((cr + br) + ar);
        float z = fast_sigm((cz + bz) + az);
        float n = fast_tanh(fmaf(r, an + bn, cn));
        h = fmaf(z, h - n, n);

        if (L0) { *outp = h; outp += outstep; }
        tcur += tstep;
    }
    if (!L0)
        g_top[b * 64 + dir * 32 + lane] = h;
}

// ---------------- final linear [B,64] @ [6,64]^T + bias ----------------
__global__ void out_kernel(const float* __restrict__ Wout, const float* __restrict__ bout,
                           float* __restrict__ out)
{
    int w = (blockIdx.x * blockDim.x + threadIdx.x) >> 5;
    int lane = threadIdx.x & 31;
    if (w >= Bb) return;
    float t0 = g_top[w * 64 + lane];
    float t1 = g_top[w * 64 + 32 + lane];
#pragma unroll
    for (int o = 0; o < 6; o++) {
        float s = t0 * Wout[o * 64 + lane] + t1 * Wout[o * 64 + 32 + lane];
#pragma unroll
        for (int off = 16; off; off >>= 1) s += __shfl_xor_sync(0xffffffffu, s, off);
        if (lane == 0) out[w * 6 + o] = s + bout[o];
    }
}

// ---------------- launch ----------------
extern "C" void kernel_launch(void* const* d_in, const int* in_sizes, int n_in,
                              void* d_out, int out_size)
{
    const int*   ids     = (const int*)d_in[0];
    const int*   mask    = (const int*)d_in[1];
    const float* embed   = (const float*)d_in[2];
    const float* Wih_l0f = (const float*)d_in[3];
    const float* Whh_l0f = (const float*)d_in[4];
    const float* bih_l0f = (const float*)d_in[5];
    const float* bhh_l0f = (const float*)d_in[6];
    const float* Wih_l0b = (const float*)d_in[7];
    const float* Whh_l0b = (const float*)d_in[8];
    const float* bih_l0b = (const float*)d_in[9];
    const float* bhh_l0b = (const float*)d_in[10];
    const float* Wih_l1f = (const float*)d_in[11];
    const float* Whh_l1f = (const float*)d_in[12];
    const float* bih_l1f = (const float*)d_in[13];
    const float* bhh_l1f = (const float*)d_in[14];
    const float* Wih_l1b = (const float*)d_in[15];
    const float* Whh_l1b = (const float*)d_in[16];
    const float* bih_l1b = (const float*)d_in[17];
    const float* bhh_l1b = (const float*)d_in[18];
    const float* Wout    = (const float*)d_in[19];
    const float* bout    = (const float*)d_in[20];
    float* out = (float*)d_out;

    float *p_embedW = nullptr, *p_x1 = nullptr, *p_gi1 = nullptr;
    cudaGetSymbolAddress((void**)&p_embedW, g_embedW);
    cudaGetSymbolAddress((void**)&p_x1, g_x1);
    cudaGetSymbolAddress((void**)&p_gi1, g_gi1);

    static int smem_set = 0;
    if (!smem_set) {
        cudaFuncSetAttribute(gemm192_kernel, cudaFuncAttributeMaxDynamicSharedMemorySize, GEMM_SMEM);
        smem_set = 1;
    }

    // 1) lengths
    lens_kernel<<<8, 1024>>>(mask);
    // 2) embedW = embed @ [Wih_l0f;Wih_l0b]^T + bias
    gemm192_kernel<<<(Vv + 63) / 64, 256, GEMM_SMEM>>>(embed, Wih_l0f, Wih_l0b, bih_l0f, bih_l0b,
                                                       p_embedW, Vv, Ee, nullptr);
    // 3) layer-0 bidirectional recurrence -> x1
    gru_kernel<true><<<128, 128>>>(p_embedW, ids, Whh_l0f, bhh_l0f, Whh_l0b, bhh_l0b);
    // 4) gi1 = x1 @ [Wih_l1f;Wih_l1b]^T + bias (masked blocks skipped)
    gemm192_kernel<<<(Bb * Tt) / 64, 256, GEMM_SMEM>>>(p_x1, Wih_l1f, Wih_l1b, bih_l1f, bih_l1b,
                                                       p_gi1, Bb * Tt, 64, mask);
    // 5) layer-1 recurrence -> final hiddens
    gru_kernel<false><<<128, 128>>>(p_gi1, nullptr, Whh_l1f, bhh_l1f, Whh_l1b, bhh_l1b);
    // 6) output projection
    out_kernel<<<8, 1024>>>(Wout, bout, out);
}

// round 4
// speedup vs baseline: 1.6598x; 1.1141x over previous
#include <cuda_runtime.h>

typedef unsigned long long ull;

#define Bb 256
#define Tt 512
#define Vv 30000
#define Ee 256

// ---------------- static device scratch ----------------
__device__ float g_embedW[(size_t)Vv * 192];       // [V][192] fwd 0..95, bwd 96..191 (bih folded, r/z cols pre-halved)
__device__ float g_x1[(size_t)Bb * Tt * 64];       // layer0 outputs [B][T][64]
__device__ float g_gi1[(size_t)Bb * Tt * 192];     // layer1 input gates (r/z cols pre-halved)
__device__ float g_top[Bb * 64];
__device__ int   g_len[Bb];

// ---------------- fast math ----------------
__device__ __forceinline__ float fast_tanh(float x) {
    float y; asm("tanh.approx.f32 %0, %1;" : "=f"(y) : "f"(x));
    return y;
}
// packed fp32x2 ops
__device__ __forceinline__ void fma2(ull& d, ull a, ull b) {
    asm("fma.rn.f32x2 %0, %1, %2, %0;" : "+l"(d) : "l"(a), "l"(b));
}
__device__ __forceinline__ ull add2(ull a, ull b) {
    ull r; asm("add.rn.f32x2 %0, %1, %2;" : "=l"(r) : "l"(a), "l"(b));
    return r;
}
__device__ __forceinline__ ull dup2(float v) {
    ull r; asm("mov.b64 %0, {%1, %1};" : "=l"(r) : "f"(v));
    return r;
}
__device__ __forceinline__ ull pack2(float lo, float hi) {
    ull r; asm("mov.b64 %0, {%1, %2};" : "=l"(r) : "f"(lo), "f"(hi));
    return r;
}
__device__ __forceinline__ float hsum2(ull v) {
    unsigned lo, hi;
    asm("mov.b64 {%0, %1}, %2;" : "=r"(lo), "=r"(hi) : "l"(v));
    return __uint_as_float(lo) + __uint_as_float(hi);
}

// ---------------- lengths from attention mask (prefix mask) ----------------
__global__ void lens_kernel(const int* __restrict__ mask)
{
    int w = (blockIdx.x * blockDim.x + threadIdx.x) >> 5;
    int lane = threadIdx.x & 31;
    if (w >= Bb) return;
    int s = 0;
    for (int i = lane; i < Tt; i += 32) s += mask[w * Tt + i];
#pragma unroll
    for (int off = 16; off; off >>= 1) s += __shfl_xor_sync(0xffffffffu, s, off);
    if (lane == 0) g_len[w] = s;
}

// ---------------- fused GEMM: C[M,192] = (A[M,K] @ [Wf;Wb]^T + bias) * colscale ----------------
// BM=64, BN=192, BK=16, 256 threads, single-buffer smem, 3 CTAs/SM.
// colscale: r/z gate columns (j=0,1,3,4) pre-multiplied by 0.5 for tanh-form sigmoid.
__global__ __launch_bounds__(256, 3)
void gemm192_kernel(const float* __restrict__ A,
                    const float* __restrict__ Wf, const float* __restrict__ Wb,
                    const float* __restrict__ bf, const float* __restrict__ bb_,
                    float* __restrict__ C, int M, int K,
                    const int* __restrict__ rowmask)
{
    __shared__ float As[16][68];
    __shared__ float Bs[16][196];

    int m0 = blockIdx.x * 64;
    if (rowmask && rowmask[m0] == 0) return;   // prefix mask: whole 64-row block padded

    int tid = threadIdx.x;
    int tx = tid & 31;        // cols tx + 32*j, j=0..5
    int ty = tid >> 5;        // rows ty*8 .. ty*8+7
    int lkk = tid & 15;
    int lrow = tid >> 4;

    // base addresses (addresses recomputed per tile; minimal register cost)
    const float* abase = A + (m0 + lrow) * K + lkk;     // + 16p*K + k0
    const float* wfb = Wf + lrow * K + lkk;             // rows lrow+16p, p=0..5
    const float* wbb = Wb + lrow * K + lkk;             // rows lrow+16(p-6), p=6..11
    bool arow_ok[4];
#pragma unroll
    for (int p = 0; p < 4; p++) arow_ok[p] = (m0 + lrow + 16 * p) < M;
    int K16 = K * 16;

    ull acc[4][6];
#pragma unroll
    for (int i = 0; i < 4; i++)
#pragma unroll
        for (int j = 0; j < 6; j++) acc[i][j] = 0ull;

    for (int k0 = 0; k0 < K; k0 += 16) {
#pragma unroll
        for (int p = 0; p < 4; p++)
            As[lkk][lrow + 16 * p] = arow_ok[p] ? abase[p * K16 + k0] : 0.f;
#pragma unroll
        for (int p = 0; p < 6; p++)
            Bs[lkk][lrow + 16 * p] = wfb[p * K16 + k0];
#pragma unroll
        for (int p = 6; p < 12; p++)
            Bs[lkk][lrow + 16 * p] = wbb[(p - 6) * K16 + k0];
        __syncthreads();
#pragma unroll
        for (int k = 0; k < 16; k++) {
            ulonglong2 q0 = *(const ulonglong2*)&As[k][ty * 8];
            ulonglong2 q1 = *(const ulonglong2*)&As[k][ty * 8 + 4];
            ull a2[4] = { q0.x, q0.y, q1.x, q1.y };
            ull b2[6];
#pragma unroll
            for (int j = 0; j < 6; j++) b2[j] = dup2(Bs[k][tx + 32 * j]);
#pragma unroll
            for (int i = 0; i < 4; i++)
#pragma unroll
                for (int j = 0; j < 6; j++)
                    fma2(acc[i][j], a2[i], b2[j]);
        }
        __syncthreads();
    }

#pragma unroll
    for (int j = 0; j < 6; j++) {
        int n = tx + 32 * j;
        // j: 0=r_f 1=z_f 2=n_f 3=r_b 4=z_b 5=n_b ; r/z pre-halved for tanh-sigmoid
        float scale = (j == 2 || j == 5) ? 1.0f : 0.5f;
        float bias = (j < 3) ? bf[n] : bb_[n - 96];
#pragma unroll
        for (int i = 0; i < 4; i++) {
            int gm0 = m0 + ty * 8 + 2 * i;
            unsigned lo, hi;
            asm("mov.b64 {%0, %1}, %2;" : "=r"(lo), "=r"(hi) : "l"(acc[i][j]));
            if (gm0 < M)     C[gm0 * 192 + n]       = (__uint_as_float(lo) + bias) * scale;
            if (gm0 + 1 < M) C[(gm0 + 1) * 192 + n] = (__uint_as_float(hi) + bias) * scale;
        }
    }
}

// ---------------- GRU recurrence: warp = (batch, dir) ----------------
template<bool L0>
__global__ __launch_bounds__(128)
void gru_kernel(const float* __restrict__ gi,
                const int* __restrict__ ids,
                const float* __restrict__ Whh_f, const float* __restrict__ bhh_f,
                const float* __restrict__ Whh_b, const float* __restrict__ bhh_b)
{
    __shared__ float sh[4][2][32];        // [warp][parity][lane]
    __shared__ int   sid[4][Tt];          // L0 only

    int wib = threadIdx.x >> 5;
    int lane = threadIdx.x & 31;
    int w = blockIdx.x * 4 + wib;
    int dir = w & 1;
    int b   = w >> 1;
    const float* Whh = dir ? Whh_b : Whh_f;
    const float* bhh = dir ? bhh_b : bhh_f;

    // pack Whh rows into f32x2 pairs; r/z rows pre-halved (tanh-form sigmoid)
    ull Wr2[16], Wz2[16], Wn2[16];
#pragma unroll
    for (int q = 0; q < 8; q++) {
        float4 v;
        v = *(const float4*)&Whh[lane * 32 + q * 4];
        Wr2[2*q]   = pack2(0.5f * v.x, 0.5f * v.y);
        Wr2[2*q+1] = pack2(0.5f * v.z, 0.5f * v.w);
        v = *(const float4*)&Whh[(32 + lane) * 32 + q * 4];
        Wz2[2*q]   = pack2(0.5f * v.x, 0.5f * v.y);
        Wz2[2*q+1] = pack2(0.5f * v.z, 0.5f * v.w);
        v = *(const float4*)&Whh[(64 + lane) * 32 + q * 4];
        Wn2[2*q]   = pack2(v.x, v.y);
        Wn2[2*q+1] = pack2(v.z, v.w);
    }
    float br = 0.5f * bhh[lane], bz = 0.5f * bhh[32 + lane], bn = bhh[64 + lane];

    int len = g_len[b];

    if (L0) {
        const int* idrow = ids + b * Tt;
        for (int i = lane; i < len; i += 32) sid[wib][i] = idrow[i];
        __syncwarp();
    }

    int tstep = dir ? -1 : 1;
    int tcur  = dir ? (len - 1) : 0;

    auto gip = [&](int t) -> const float* {
        if (L0) return gi + sid[wib][t] * 192 + dir * 96;
        else    return gi + (b * Tt + t) * 192 + dir * 96;
    };

    // distance-3 prefetch pipeline
    const float* p = gip(tcur);
    float p0r = __ldg(p + lane), p0z = __ldg(p + 32 + lane), p0n = __ldg(p + 64 + lane);
    float p1r = p0r, p1z = p0z, p1n = p0n;
    float p2r = p0r, p2z = p0z, p2n = p0n;
    if (len > 1) {
        p = gip(tcur + tstep);
        p1r = __ldg(p + lane); p1z = __ldg(p + 32 + lane); p1n = __ldg(p + 64 + lane);
    }
    if (len > 2) {
        p = gip(tcur + 2 * tstep);
        p2r = __ldg(p + lane); p2z = __ldg(p + 32 + lane); p2n = __ldg(p + 64 + lane);
    }

    float h = 0.f;
    float* outp = L0 ? (g_x1 + (b * Tt + tcur) * 64 + dir * 32 + lane) : nullptr;
    int outstep = tstep * 64;

    for (int s = 0; s < len; s++) {
        float cr = p0r, cz = p0z, cn = p0n;
        p0r = p1r; p0z = p1z; p0n = p1n;
        p1r = p2r; p1z = p2z; p1n = p2n;
        if (s + 3 < len) {
            p = gip(tcur + 3 * tstep);
            p2r = __ldg(p + lane); p2z = __ldg(p + 32 + lane); p2n = __ldg(p + 64 + lane);
        }

        // broadcast h via parity-buffered smem
        int par = s & 1;
        sh[wib][par][lane] = h;
        __syncwarp();
        ull h2[16];
#pragma unroll
        for (int i = 0; i < 8; i++) {
            ulonglong2 q2 = *(const ulonglong2*)&sh[wib][par][4 * i];
            h2[2 * i] = q2.x; h2[2 * i + 1] = q2.y;
        }

        ull ra = 0ull, rb = 0ull, za = 0ull, zb = 0ull, na = 0ull, nb2 = 0ull;
#pragma unroll
        for (int k = 0; k < 16; k += 2) {
            fma2(ra, Wr2[k],     h2[k]);
            fma2(rb, Wr2[k + 1], h2[k + 1]);
            fma2(za, Wz2[k],     h2[k]);
            fma2(zb, Wz2[k + 1], h2[k + 1]);
            fma2(na, Wn2[k],     h2[k]);
            fma2(nb2, Wn2[k + 1], h2[k + 1]);
        }
        float ar = hsum2(add2(ra, rb));
        float az = hsum2(add2(za, zb));
        float an = hsum2(add2(na, nb2));

        // sigmoid(x) = 0.5 + 0.5*tanh(x/2); args already half-scaled
        float r = fmaf(0.5f, fast_tanh((cr + br) + ar), 0.5f);
        float z = fmaf(0.5f, fast_tanh((cz + bz) + az), 0.5f);
        float n = fast_tanh(fmaf(r, an + bn, cn));
        h = fmaf(z, h - n, n);

        if (L0) { *outp = h; outp += outstep; }
        tcur += tstep;
    }
    if (!L0)
        g_top[b * 64 + dir * 32 + lane] = h;
}

// ---------------- final linear [B,64] @ [6,64]^T + bias ----------------
__global__ void out_kernel(const float* __restrict__ Wout, const float* __restrict__ bout,
                           float* __restrict__ out)
{
    int w = (blockIdx.x * blockDim.x + threadIdx.x) >> 5;
    int lane = threadIdx.x & 31;
    if (w >= Bb) return;
    float t0 = g_top[w * 64 + lane];
    float t1 = g_top[w * 64 + 32 + lane];
#pragma unroll
    for (int o = 0; o < 6; o++) {
        float s = t0 * Wout[o * 64 + lane] + t1 * Wout[o * 64 + 32 + lane];
#pragma unroll
        for (int off = 16; off; off >>= 1) s += __shfl_xor_sync(0xffffffffu, s, off);
        if (lane == 0) out[w * 6 + o] = s + bout[o];
    }
}

// ---------------- launch ----------------
extern "C" void kernel_launch(void* const* d_in, const int* in_sizes, int n_in,
                              void* d_out, int out_size)
{
    const int*   ids     = (const int*)d_in[0];
    const int*   mask    = (const int*)d_in[1];
    const float* embed   = (const float*)d_in[2];
    const float* Wih_l0f = (const float*)d_in[3];
    const float* Whh_l0f = (const float*)d_in[4];
    const float* bih_l0f = (const float*)d_in[5];
    const float* bhh_l0f = (const float*)d_in[6];
    const float* Wih_l0b = (const float*)d_in[7];
    const float* Whh_l0b = (const float*)d_in[8];
    const float* bih_l0b = (const float*)d_in[9];
    const float* bhh_l0b = (const float*)d_in[10];
    const float* Wih_l1f = (const float*)d_in[11];
    const float* Whh_l1f = (const float*)d_in[12];
    const float* bih_l1f = (const float*)d_in[13];
    const float* bhh_l1f = (const float*)d_in[14];
    const float* Wih_l1b = (const float*)d_in[15];
    const float* Whh_l1b = (const float*)d_in[16];
    const float* bih_l1b = (const float*)d_in[17];
    const float* bhh_l1b = (const float*)d_in[18];
    const float* Wout    = (const float*)d_in[19];
    const float* bout    = (const float*)d_in[20];
    float* out = (float*)d_out;

    float *p_embedW = nullptr, *p_x1 = nullptr, *p_gi1 = nullptr;
    cudaGetSymbolAddress((void**)&p_embedW, g_embedW);
    cudaGetSymbolAddress((void**)&p_x1, g_x1);
    cudaGetSymbolAddress((void**)&p_gi1, g_gi1);

    // 1) lengths
    lens_kernel<<<8, 1024>>>(mask);
    // 2) embedW = (embed @ [Wih_l0f;Wih_l0b]^T + bias) * colscale
    gemm192_kernel<<<(Vv + 63) / 64, 256>>>(embed, Wih_l0f, Wih_l0b, bih_l0f, bih_l0b,
                                            p_embedW, Vv, Ee, nullptr);
    // 3) layer-0 bidirectional recurrence -> x1
    gru_kernel<true><<<128, 128>>>(p_embedW, ids, Whh_l0f, bhh_l0f, Whh_l0b, bhh_l0b);
    // 4) gi1 = (x1 @ [Wih_l1f;Wih_l1b]^T + bias) * colscale  (masked blocks skipped)
    gemm192_kernel<<<(Bb * Tt) / 64, 256>>>(p_x1, Wih_l1f, Wih_l1b, bih_l1f, bih_l1b,
                                            p_gi1, Bb * Tt, 64, mask);
    // 5) layer-1 recurrence -> final hiddens
    gru_kernel<false><<<128, 128>>>(p_gi1, nullptr, Whh_l1f, bhh_l1f, Whh_l1b, bhh_l1b);
    // 6) output projection
    out_kernel<<<8, 1024>>>(Wout, bout, out);
}

// round 5
// speedup vs baseline: 1.7803x; 1.0726x over previous
#include <cuda_runtime.h>

typedef unsigned long long ull;

#define Bb 256
#define Tt 512
#define Vv 30000
#define Ee 256

// ---------------- static device scratch ----------------
__device__ float g_embedW[(size_t)Vv * 192];       // [V][192] fwd 0..95, bwd 96..191 (bih folded, r/z pre-halved)
__device__ float g_x1[(size_t)Bb * Tt * 64];       // layer0 outputs [B][T][64]
__device__ float g_gi1[(size_t)Bb * Tt * 192];     // layer1 input gates (r/z pre-halved)
__device__ float g_top[Bb * 64];
__device__ int   g_len[Bb];

// ---------------- fast math ----------------
__device__ __forceinline__ float fast_tanh(float x) {
    float y; asm("tanh.approx.f32 %0, %1;" : "=f"(y) : "f"(x));
    return y;
}
__device__ __forceinline__ void fma2(ull& d, ull a, ull b) {
    asm("fma.rn.f32x2 %0, %1, %2, %0;" : "+l"(d) : "l"(a), "l"(b));
}
__device__ __forceinline__ ull add2(ull a, ull b) {
    ull r; asm("add.rn.f32x2 %0, %1, %2;" : "=l"(r) : "l"(a), "l"(b));
    return r;
}
__device__ __forceinline__ ull dup2(float v) {
    ull r; asm("mov.b64 %0, {%1, %1};" : "=l"(r) : "f"(v));
    return r;
}
__device__ __forceinline__ ull pack2(float lo, float hi) {
    ull r; asm("mov.b64 %0, {%1, %2};" : "=l"(r) : "f"(lo), "f"(hi));
    return r;
}
__device__ __forceinline__ float hsum2(ull v) {
    unsigned lo, hi;
    asm("mov.b64 {%0, %1}, %2;" : "=r"(lo), "=r"(hi) : "l"(v));
    return __uint_as_float(lo) + __uint_as_float(hi);
}

// ---------------- lengths from attention mask (prefix mask) ----------------
__global__ void lens_kernel(const int* __restrict__ mask)
{
    int w = (blockIdx.x * blockDim.x + threadIdx.x) >> 5;
    int lane = threadIdx.x & 31;
    if (w >= Bb) return;
    int s = 0;
    for (int i = lane; i < Tt; i += 32) s += mask[w * Tt + i];
#pragma unroll
    for (int off = 16; off; off >>= 1) s += __shfl_xor_sync(0xffffffffu, s, off);
    if (lane == 0) g_len[w] = s;
}

// ---------------- fused GEMM: C[M,192] = (A[M,K] @ [Wf;Wb]^T + bias) * colscale ----------------
// BM=128, BN=192, BK=16, 256 threads. Microtile 16 rows (8 f32x2 pairs) x 6 cols.
// 48 fma2 per k vs ~32 other issue slots -> ~75% fma2 density per warp.
__global__ __launch_bounds__(256)
void gemm192_kernel(const float* __restrict__ A,
                    const float* __restrict__ Wf, const float* __restrict__ Wb,
                    const float* __restrict__ bf, const float* __restrict__ bb_,
                    float* __restrict__ C, int M, int K,
                    const int* __restrict__ rowmask)
{
    __shared__ float As[16][132];
    __shared__ float Bs[16][196];

    int m0 = blockIdx.x * 128;
    if (rowmask && rowmask[m0] == 0) return;   // prefix mask: whole 128-row block padded

    int tid = threadIdx.x;
    int tx = tid & 31;        // cols tx + 32*j, j=0..5 (warp-uniform ty -> A reads broadcast)
    int ty = tid >> 5;        // rows ty*16 .. ty*16+15
    int lkk = tid & 15;
    int lrow = tid >> 4;      // 0..15

    // A load rows (clamped; stores guarded)
    size_t arow[8];
#pragma unroll
    for (int p = 0; p < 8; p++) {
        int gm = m0 + lrow + 16 * p;
        if (gm > M - 1) gm = M - 1;
        arow[p] = (size_t)gm * K + lkk;
    }
    const float* wfb = Wf + lrow * K + lkk;
    const float* wbb = Wb + lrow * K + lkk;
    int K16 = K * 16;

    ull acc[8][6];
#pragma unroll
    for (int i = 0; i < 8; i++)
#pragma unroll
        for (int j = 0; j < 6; j++) acc[i][j] = 0ull;

    for (int k0 = 0; k0 < K; k0 += 16) {
#pragma unroll
        for (int p = 0; p < 8; p++)
            As[lkk][lrow + 16 * p] = A[arow[p] + k0];
#pragma unroll
        for (int p = 0; p < 6; p++)
            Bs[lkk][lrow + 16 * p] = wfb[p * K16 + k0];
#pragma unroll
        for (int p = 6; p < 12; p++)
            Bs[lkk][lrow + 16 * p] = wbb[(p - 6) * K16 + k0];
        __syncthreads();
#pragma unroll
        for (int k = 0; k < 16; k++) {
            ull a2[8];
#pragma unroll
            for (int q = 0; q < 4; q++) {
                ulonglong2 v = *(const ulonglong2*)&As[k][ty * 16 + 4 * q];
                a2[2 * q] = v.x; a2[2 * q + 1] = v.y;
            }
            ull b2[6];
#pragma unroll
            for (int j = 0; j < 6; j++) b2[j] = dup2(Bs[k][tx + 32 * j]);
#pragma unroll
            for (int i = 0; i < 8; i++)
#pragma unroll
                for (int j = 0; j < 6; j++)
                    fma2(acc[i][j], a2[i], b2[j]);
        }
        __syncthreads();
    }

#pragma unroll
    for (int j = 0; j < 6; j++) {
        int n = tx + 32 * j;
        // j: 0=r_f 1=z_f 2=n_f 3=r_b 4=z_b 5=n_b ; r/z pre-halved for tanh-form sigmoid
        float scale = (j == 2 || j == 5) ? 1.0f : 0.5f;
        float bias = (j < 3) ? bf[n] : bb_[n - 96];
#pragma unroll
        for (int i = 0; i < 8; i++) {
            int gm0 = m0 + ty * 16 + 2 * i;
            unsigned lo, hi;
            asm("mov.b64 {%0, %1}, %2;" : "=r"(lo), "=r"(hi) : "l"(acc[i][j]));
            if (gm0 < M)     C[(size_t)gm0 * 192 + n]       = (__uint_as_float(lo) + bias) * scale;
            if (gm0 + 1 < M) C[(size_t)(gm0 + 1) * 192 + n] = (__uint_as_float(hi) + bias) * scale;
        }
    }
}

// ---------------- GRU recurrence: warp = (batch, dir) ----------------
template<bool L0>
__global__ __launch_bounds__(128)
void gru_kernel(const float* __restrict__ gi,
                const int* __restrict__ ids,
                const float* __restrict__ Whh_f, const float* __restrict__ bhh_f,
                const float* __restrict__ Whh_b, const float* __restrict__ bhh_b)
{
    __shared__ float sh[4][2][32];        // [warp][parity][lane]
    __shared__ int   sid[4][Tt];          // L0 only

    int wib = threadIdx.x >> 5;
    int lane = threadIdx.x & 31;
    int w = blockIdx.x * 4 + wib;
    int dir = w & 1;
    int b   = w >> 1;
    const float* Whh = dir ? Whh_b : Whh_f;
    const float* bhh = dir ? bhh_b : bhh_f;

    // Whh rows packed as f32x2 pairs; r/z rows pre-halved (tanh-form sigmoid)
    ull Wr2[16], Wz2[16], Wn2[16];
#pragma unroll
    for (int q = 0; q < 8; q++) {
        float4 v;
        v = *(const float4*)&Whh[lane * 32 + q * 4];
        Wr2[2*q]   = pack2(0.5f * v.x, 0.5f * v.y);
        Wr2[2*q+1] = pack2(0.5f * v.z, 0.5f * v.w);
        v = *(const float4*)&Whh[(32 + lane) * 32 + q * 4];
        Wz2[2*q]   = pack2(0.5f * v.x, 0.5f * v.y);
        Wz2[2*q+1] = pack2(0.5f * v.z, 0.5f * v.w);
        v = *(const float4*)&Whh[(64 + lane) * 32 + q * 4];
        Wn2[2*q]   = pack2(v.x, v.y);
        Wn2[2*q+1] = pack2(v.z, v.w);
    }
    // biases folded into accumulator init
    ull bR = pack2(0.5f * bhh[lane], 0.f);
    ull bZ = pack2(0.5f * bhh[32 + lane], 0.f);
    ull bN = pack2(bhh[64 + lane], 0.f);

    int len = g_len[b];

    if (L0) {
        const int* idrow = ids + b * Tt;
        for (int i = lane; i < len; i += 32) sid[wib][i] = idrow[i];
        __syncwarp();
    }

    int tstep = dir ? -1 : 1;
    int tcur  = dir ? (len - 1) : 0;
    long gistride = (long)tstep * 192;

    // L1 running pointer; L0 uses id gather
    const float* giptr = gi + ((size_t)b * Tt + tcur) * 192 + dir * 96;  // L1 base

    auto gip = [&](int s3) -> const float* {   // pointer for step s3 ahead of tcur
        if (L0) return gi + (size_t)sid[wib][tcur + s3 * tstep] * 192 + dir * 96;
        else    return giptr + (long)s3 * gistride;
    };

    // distance-3 prefetch pipeline
    const float* p = gip(0);
    float p0r = __ldg(p + lane), p0z = __ldg(p + 32 + lane), p0n = __ldg(p + 64 + lane);
    float p1r = p0r, p1z = p0z, p1n = p0n;
    float p2r = p0r, p2z = p0z, p2n = p0n;
    if (len > 1) { p = gip(1); p1r = __ldg(p + lane); p1z = __ldg(p + 32 + lane); p1n = __ldg(p + 64 + lane); }
    if (len > 2) { p = gip(2); p2r = __ldg(p + lane); p2z = __ldg(p + 32 + lane); p2n = __ldg(p + 64 + lane); }

    float h = 0.f;
    float* outp = L0 ? (g_x1 + ((size_t)b * Tt + tcur) * 64 + dir * 32 + lane) : nullptr;
    int outstep = tstep * 64;

    for (int s = 0; s < len; s++) {
        float cr = p0r, cz = p0z, cn = p0n;
        p0r = p1r; p0z = p1z; p0n = p1n;
        p1r = p2r; p1z = p2z; p1n = p2n;
        if (s + 3 < len) {
            p = gip(3);
            p2r = __ldg(p + lane); p2z = __ldg(p + 32 + lane); p2n = __ldg(p + 64 + lane);
        }

        int par = s & 1;
        sh[wib][par][lane] = h;
        __syncwarp();
        ull h2[16];
#pragma unroll
        for (int i = 0; i < 8; i++) {
            ulonglong2 q2 = *(const ulonglong2*)&sh[wib][par][4 * i];
            h2[2 * i] = q2.x; h2[2 * i + 1] = q2.y;
        }

        ull ra = bR, rb = 0ull, za = bZ, zb = 0ull, na = bN, nb2 = 0ull;
#pragma unroll
        for (int k = 0; k < 16; k += 2) {
            fma2(na,  Wn2[k],     h2[k]);
            fma2(nb2, Wn2[k + 1], h2[k + 1]);
            fma2(ra,  Wr2[k],     h2[k]);
            fma2(rb,  Wr2[k + 1], h2[k + 1]);
            fma2(za,  Wz2[k],     h2[k]);
            fma2(zb,  Wz2[k + 1], h2[k + 1]);
        }
        float ar = hsum2(add2(ra, rb));
        float az = hsum2(add2(za, zb));
        float an = hsum2(add2(na, nb2));

        // sigmoid(x) = 0.5 + 0.5*tanh(x/2); r/z args pre-halved upstream
        float r = fmaf(0.5f, fast_tanh(cr + ar), 0.5f);
        float z = fmaf(0.5f, fast_tanh(cz + az), 0.5f);
        float n = fast_tanh(fmaf(r, an, cn));
        h = fmaf(z, h - n, n);

        if (L0) { *outp = h; outp += outstep; }
        else    { giptr += gistride; }
        tcur += tstep;
    }
    if (!L0)
        g_top[b * 64 + dir * 32 + lane] = h;
}

// ---------------- final linear [B,64] @ [6,64]^T + bias ----------------
__global__ void out_kernel(const float* __restrict__ Wout, const float* __restrict__ bout,
                           float* __restrict__ out)
{
    int w = (blockIdx.x * blockDim.x + threadIdx.x) >> 5;
    int lane = threadIdx.x & 31;
    if (w >= Bb) return;
    float t0 = g_top[w * 64 + lane];
    float t1 = g_top[w * 64 + 32 + lane];
#pragma unroll
    for (int o = 0; o < 6; o++) {
        float s = t0 * Wout[o * 64 + lane] + t1 * Wout[o * 64 + 32 + lane];
#pragma unroll
        for (int off = 16; off; off >>= 1) s += __shfl_xor_sync(0xffffffffu, s, off);
        if (lane == 0) out[w * 6 + o] = s + bout[o];
    }
}

// ---------------- launch ----------------
extern "C" void kernel_launch(void* const* d_in, const int* in_sizes, int n_in,
                              void* d_out, int out_size)
{
    const int*   ids     = (const int*)d_in[0];
    const int*   mask    = (const int*)d_in[1];
    const float* embed   = (const float*)d_in[2];
    const float* Wih_l0f = (const float*)d_in[3];
    const float* Whh_l0f = (const float*)d_in[4];
    const float* bih_l0f = (const float*)d_in[5];
    const float* bhh_l0f = (const float*)d_in[6];
    const float* Wih_l0b = (const float*)d_in[7];
    const float* Whh_l0b = (const float*)d_in[8];
    const float* bih_l0b = (const float*)d_in[9];
    const float* bhh_l0b = (const float*)d_in[10];
    const float* Wih_l1f = (const float*)d_in[11];
    const float* Whh_l1f = (const float*)d_in[12];
    const float* bih_l1f = (const float*)d_in[13];
    const float* bhh_l1f = (const float*)d_in[14];
    const float* Wih_l1b = (const float*)d_in[15];
    const float* Whh_l1b = (const float*)d_in[16];
    const float* bih_l1b = (const float*)d_in[17];
    const float* bhh_l1b = (const float*)d_in[18];
    const float* Wout    = (const float*)d_in[19];
    const float* bout    = (const float*)d_in[20];
    float* out = (float*)d_out;

    float *p_embedW = nullptr, *p_x1 = nullptr, *p_gi1 = nullptr;
    cudaGetSymbolAddress((void**)&p_embedW, g_embedW);
    cudaGetSymbolAddress((void**)&p_x1, g_x1);
    cudaGetSymbolAddress((void**)&p_gi1, g_gi1);

    // 1) lengths
    lens_kernel<<<8, 1024>>>(mask);
    // 2) embedW = (embed @ [Wih_l0f;Wih_l0b]^T + bias) * colscale
    gemm192_kernel<<<(Vv + 127) / 128, 256>>>(embed, Wih_l0f, Wih_l0b, bih_l0f, bih_l0b,
                                              p_embedW, Vv, Ee, nullptr);
    // 3) layer-0 bidirectional recurrence -> x1
    gru_kernel<true><<<128, 128>>>(p_embedW, ids, Whh_l0f, bhh_l0f, Whh_l0b, bhh_l0b);
    // 4) gi1 = (x1 @ [Wih_l1f;Wih_l1b]^T + bias) * colscale  (masked blocks skipped)
    gemm192_kernel<<<(Bb * Tt) / 128, 256>>>(p_x1, Wih_l1f, Wih_l1b, bih_l1f, bih_l1b,
                                             p_gi1, Bb * Tt, 64, mask);
    // 5) layer-1 recurrence -> final hiddens
    gru_kernel<false><<<128, 128>>>(p_gi1, nullptr, Whh_l1f, bhh_l1f, Whh_l1b, bhh_l1b);
    // 6) output projection
    out_kernel<<<8, 1024>>>(Wout, bout, out);
}

// round 6
// speedup vs baseline: 2.0237x; 1.1367x over previous
#include <cuda_runtime.h>

typedef unsigned long long ull;

#define Bb 256
#define Tt 512
#define Vv 30000
#define Ee 256

// ---------------- static device scratch ----------------
__device__ float g_embedW[(size_t)Vv * 192];       // [V][192] fwd 0..95, bwd 96..191 (bih folded, r/z pre-halved)
__device__ float g_x1[(size_t)Bb * Tt * 64];       // layer0 outputs [B][T][64]
__device__ float g_gi1[(size_t)Bb * Tt * 192];     // layer1 input gates (r/z pre-halved)
__device__ float g_top[Bb * 64];
__device__ int   g_len[Bb];

// ---------------- fast math ----------------
__device__ __forceinline__ float fast_tanh(float x) {
    float y; asm("tanh.approx.f32 %0, %1;" : "=f"(y) : "f"(x));
    return y;
}
__device__ __forceinline__ void fma2(ull& d, ull a, ull b) {
    asm("fma.rn.f32x2 %0, %1, %2, %0;" : "+l"(d) : "l"(a), "l"(b));
}
__device__ __forceinline__ ull add2(ull a, ull b) {
    ull r; asm("add.rn.f32x2 %0, %1, %2;" : "=l"(r) : "l"(a), "l"(b));
    return r;
}
__device__ __forceinline__ ull dup2(float v) {
    ull r; asm("mov.b64 %0, {%1, %1};" : "=l"(r) : "f"(v));
    return r;
}
__device__ __forceinline__ ull pack2(float lo, float hi) {
    ull r; asm("mov.b64 %0, {%1, %2};" : "=l"(r) : "f"(lo), "f"(hi));
    return r;
}
__device__ __forceinline__ float hsum2(ull v) {
    unsigned lo, hi;
    asm("mov.b64 {%0, %1}, %2;" : "=r"(lo), "=r"(hi) : "l"(v));
    return __uint_as_float(lo) + __uint_as_float(hi);
}

// ---------------- lengths from attention mask (prefix mask) ----------------
__global__ void lens_kernel(const int* __restrict__ mask)
{
    int w = (blockIdx.x * blockDim.x + threadIdx.x) >> 5;
    int lane = threadIdx.x & 31;
    if (w >= Bb) return;
    int s = 0;
    for (int i = lane; i < Tt; i += 32) s += mask[w * Tt + i];
#pragma unroll
    for (int off = 16; off; off >>= 1) s += __shfl_xor_sync(0xffffffffu, s, off);
    if (lane == 0) g_len[w] = s;
}

// ---------------- fused GEMM: C[M,192] = (A[M,K] @ [Wf;Wb]^T + bias) * colscale ----------------
// BM=64, BN=192, BK=16, 256 threads, single-buffer smem, 3 CTAs/SM.  (R4 proven config)
__global__ __launch_bounds__(256, 3)
void gemm192_kernel(const float* __restrict__ A,
                    const float* __restrict__ Wf, const float* __restrict__ Wb,
                    const float* __restrict__ bf, const float* __restrict__ bb_,
                    float* __restrict__ C, int M, int K,
                    const int* __restrict__ rowmask)
{
    __shared__ float As[16][68];
    __shared__ float Bs[16][196];

    int m0 = blockIdx.x * 64;
    if (rowmask && rowmask[m0] == 0) return;   // prefix mask: whole 64-row block padded

    int tid = threadIdx.x;
    int tx = tid & 31;        // cols tx + 32*j, j=0..5
    int ty = tid >> 5;        // rows ty*8 .. ty*8+7
    int lkk = tid & 15;
    int lrow = tid >> 4;

    const float* abase = A + (m0 + lrow) * K + lkk;
    const float* wfb = Wf + lrow * K + lkk;
    const float* wbb = Wb + lrow * K + lkk;
    bool arow_ok[4];
#pragma unroll
    for (int p = 0; p < 4; p++) arow_ok[p] = (m0 + lrow + 16 * p) < M;
    int K16 = K * 16;

    ull acc[4][6];
#pragma unroll
    for (int i = 0; i < 4; i++)
#pragma unroll
        for (int j = 0; j < 6; j++) acc[i][j] = 0ull;

    for (int k0 = 0; k0 < K; k0 += 16) {
#pragma unroll
        for (int p = 0; p < 4; p++)
            As[lkk][lrow + 16 * p] = arow_ok[p] ? abase[p * K16 + k0] : 0.f;
#pragma unroll
        for (int p = 0; p < 6; p++)
            Bs[lkk][lrow + 16 * p] = wfb[p * K16 + k0];
#pragma unroll
        for (int p = 6; p < 12; p++)
            Bs[lkk][lrow + 16 * p] = wbb[(p - 6) * K16 + k0];
        __syncthreads();
#pragma unroll
        for (int k = 0; k < 16; k++) {
            ulonglong2 q0 = *(const ulonglong2*)&As[k][ty * 8];
            ulonglong2 q1 = *(const ulonglong2*)&As[k][ty * 8 + 4];
            ull a2[4] = { q0.x, q0.y, q1.x, q1.y };
            ull b2[6];
#pragma unroll
            for (int j = 0; j < 6; j++) b2[j] = dup2(Bs[k][tx + 32 * j]);
#pragma unroll
            for (int i = 0; i < 4; i++)
#pragma unroll
                for (int j = 0; j < 6; j++)
                    fma2(acc[i][j], a2[i], b2[j]);
        }
        __syncthreads();
    }

#pragma unroll
    for (int j = 0; j < 6; j++) {
        int n = tx + 32 * j;
        // j: 0=r_f 1=z_f 2=n_f 3=r_b 4=z_b 5=n_b ; r/z pre-halved for tanh-form sigmoid
        float scale = (j == 2 || j == 5) ? 1.0f : 0.5f;
        float bias = (j < 3) ? bf[n] : bb_[n - 96];
#pragma unroll
        for (int i = 0; i < 4; i++) {
            int gm0 = m0 + ty * 8 + 2 * i;
            unsigned lo, hi;
            asm("mov.b64 {%0, %1}, %2;" : "=r"(lo), "=r"(hi) : "l"(acc[i][j]));
            if (gm0 < M)     C[(size_t)gm0 * 192 + n]       = (__uint_as_float(lo) + bias) * scale;
            if (gm0 + 1 < M) C[(size_t)(gm0 + 1) * 192 + n] = (__uint_as_float(hi) + bias) * scale;
        }
    }
}

// ---------------- GRU recurrence: warp = (batch, dir) ----------------
template<bool L0>
__global__ __launch_bounds__(128)
void gru_kernel(const float* __restrict__ gi,
                const int* __restrict__ ids,
                const float* __restrict__ Whh_f, const float* __restrict__ bhh_f,
                const float* __restrict__ Whh_b, const float* __restrict__ bhh_b)
{
    __shared__ float sh[4][2][32];        // [warp][parity][lane]
    __shared__ int   sid[4][Tt];          // L0 only

    int wib = threadIdx.x >> 5;
    int lane = threadIdx.x & 31;
    int w = blockIdx.x * 4 + wib;
    int dir = w & 1;
    int b   = w >> 1;
    const float* Whh = dir ? Whh_b : Whh_f;
    const float* bhh = dir ? bhh_b : bhh_f;

    // Whh rows packed as f32x2 pairs; r/z rows pre-halved (tanh-form sigmoid)
    ull Wr2[16], Wz2[16], Wn2[16];
#pragma unroll
    for (int q = 0; q < 8; q++) {
        float4 v;
        v = *(const float4*)&Whh[lane * 32 + q * 4];
        Wr2[2*q]   = pack2(0.5f * v.x, 0.5f * v.y);
        Wr2[2*q+1] = pack2(0.5f * v.z, 0.5f * v.w);
        v = *(const float4*)&Whh[(32 + lane) * 32 + q * 4];
        Wz2[2*q]   = pack2(0.5f * v.x, 0.5f * v.y);
        Wz2[2*q+1] = pack2(0.5f * v.z, 0.5f * v.w);
        v = *(const float4*)&Whh[(64 + lane) * 32 + q * 4];
        Wn2[2*q]   = pack2(v.x, v.y);
        Wn2[2*q+1] = pack2(v.z, v.w);
    }
    ull bR = pack2(0.5f * bhh[lane], 0.f);
    ull bZ = pack2(0.5f * bhh[32 + lane], 0.f);
    ull bN = pack2(bhh[64 + lane], 0.f);

    int len = g_len[b];
    int lenm1 = len - 1;

    if (L0) {
        const int* idrow = ids + b * Tt;
        for (int i = lane; i < len; i += 32) sid[wib][i] = idrow[i];
        __syncwarp();
    }

    int tstep = dir ? -1 : 1;
    int tcur  = dir ? lenm1 : 0;

    // direction-adjusted base pointers (1 IMAD per prefetch)
    const float* gi0  = gi + dir * 96;                              // L0: + sid*192
    const float* gib  = gi + (size_t)b * Tt * 192 + dir * 96;      // L1: + t*192

    // clamped time index, branch-free
    auto tclamp = [&](int t) { return min(max(t, 0), lenm1); };
    auto gip = [&](int t) -> const float* {
        if (L0) return gi0 + (size_t)sid[wib][t] * 192;
        else    return gib + (size_t)t * 192;
    };

    // distance-3 prefetch pipeline (clamped -> no init branches)
    const float* p;
    p = gip(tclamp(tcur));
    float p0r = __ldg(p + lane), p0z = __ldg(p + 32 + lane), p0n = __ldg(p + 64 + lane);
    p = gip(tclamp(tcur + tstep));
    float p1r = __ldg(p + lane), p1z = __ldg(p + 32 + lane), p1n = __ldg(p + 64 + lane);
    p = gip(tclamp(tcur + 2 * tstep));
    float p2r = __ldg(p + lane), p2z = __ldg(p + 32 + lane), p2n = __ldg(p + 64 + lane);

    float h = 0.f;
    float* outp = L0 ? (g_x1 + ((size_t)b * Tt + tcur) * 64 + dir * 32 + lane) : nullptr;
    int outstep = tstep * 64;

#pragma unroll 2
    for (int s = 0; s < len; s++) {
        float cr = p0r, cz = p0z, cn = p0n;
        p0r = p1r; p0z = p1z; p0n = p1n;
        p1r = p2r; p1z = p2z; p1n = p2n;
        // branch-free clamped prefetch (redundant tail loads are harmless)
        p = gip(tclamp(tcur + 3 * tstep));
        p2r = __ldg(p + lane); p2z = __ldg(p + 32 + lane); p2n = __ldg(p + 64 + lane);

        int par = s & 1;
        sh[wib][par][lane] = h;
        __syncwarp();
        ull h2[16];
#pragma unroll
        for (int i = 0; i < 8; i++) {
            ulonglong2 q2 = *(const ulonglong2*)&sh[wib][par][4 * i];
            h2[2 * i] = q2.x; h2[2 * i + 1] = q2.y;
        }

        ull ra = bR, rb = 0ull, za = bZ, zb = 0ull, na = bN, nb2 = 0ull;
#pragma unroll
        for (int k = 0; k < 16; k += 2) {
            fma2(na,  Wn2[k],     h2[k]);
            fma2(nb2, Wn2[k + 1], h2[k + 1]);
            fma2(ra,  Wr2[k],     h2[k]);
            fma2(rb,  Wr2[k + 1], h2[k + 1]);
            fma2(za,  Wz2[k],     h2[k]);
            fma2(zb,  Wz2[k + 1], h2[k + 1]);
        }
        float ar = hsum2(add2(ra, rb));
        float az = hsum2(add2(za, zb));
        float an = hsum2(add2(na, nb2));

        // sigmoid(x) = 0.5 + 0.5*tanh(x/2); r/z args pre-halved upstream
        float r = fmaf(0.5f, fast_tanh(cr + ar), 0.5f);
        float z = fmaf(0.5f, fast_tanh(cz + az), 0.5f);
        float n = fast_tanh(fmaf(r, an, cn));
        h = fmaf(z, h - n, n);

        if (L0) { *outp = h; outp += outstep; }
        tcur += tstep;
    }
    if (!L0)
        g_top[b * 64 + dir * 32 + lane] = h;
}

// ---------------- final linear [B,64] @ [6,64]^T + bias ----------------
__global__ void out_kernel(const float* __restrict__ Wout, const float* __restrict__ bout,
                           float* __restrict__ out)
{
    int w = (blockIdx.x * blockDim.x + threadIdx.x) >> 5;
    int lane = threadIdx.x & 31;
    if (w >= Bb) return;
    float t0 = g_top[w * 64 + lane];
    float t1 = g_top[w * 64 + 32 + lane];
#pragma unroll
    for (int o = 0; o < 6; o++) {
        float s = t0 * Wout[o * 64 + lane] + t1 * Wout[o * 64 + 32 + lane];
#pragma unroll
        for (int off = 16; off; off >>= 1) s += __shfl_xor_sync(0xffffffffu, s, off);
        if (lane == 0) out[w * 6 + o] = s + bout[o];
    }
}

// ---------------- launch ----------------
extern "C" void kernel_launch(void* const* d_in, const int* in_sizes, int n_in,
                              void* d_out, int out_size)
{
    const int*   ids     = (const int*)d_in[0];
    const int*   mask    = (const int*)d_in[1];
    const float* embed   = (const float*)d_in[2];
    const float* Wih_l0f = (const float*)d_in[3];
    const float* Whh_l0f = (const float*)d_in[4];
    const float* bih_l0f = (const float*)d_in[5];
    const float* bhh_l0f = (const float*)d_in[6];
    const float* Wih_l0b = (const float*)d_in[7];
    const float* Whh_l0b = (const float*)d_in[8];
    const float* bih_l0b = (const float*)d_in[9];
    const float* bhh_l0b = (const float*)d_in[10];
    const float* Wih_l1f = (const float*)d_in[11];
    const float* Whh_l1f = (const float*)d_in[12];
    const float* bih_l1f = (const float*)d_in[13];
    const float* bhh_l1f = (const float*)d_in[14];
    const float* Wih_l1b = (const float*)d_in[15];
    const float* Whh_l1b = (const float*)d_in[16];
    const float* bih_l1b = (const float*)d_in[17];
    const float* bhh_l1b = (const float*)d_in[18];
    const float* Wout    = (const float*)d_in[19];
    const float* bout    = (const float*)d_in[20];
    float* out = (float*)d_out;

    float *p_embedW = nullptr, *p_x1 = nullptr, *p_gi1 = nullptr;
    cudaGetSymbolAddress((void**)&p_embedW, g_embedW);
    cudaGetSymbolAddress((void**)&p_x1, g_x1);
    cudaGetSymbolAddress((void**)&p_gi1, g_gi1);

    // 1) lengths
    lens_kernel<<<8, 1024>>>(mask);
    // 2) embedW = (embed @ [Wih_l0f;Wih_l0b]^T + bias) * colscale
    gemm192_kernel<<<(Vv + 63) / 64, 256>>>(embed, Wih_l0f, Wih_l0b, bih_l0f, bih_l0b,
                                            p_embedW, Vv, Ee, nullptr);
    // 3) layer-0 bidirectional recurrence -> x1
    gru_kernel<true><<<128, 128>>>(p_embedW, ids, Whh_l0f, bhh_l0f, Whh_l0b, bhh_l0b);
    // 4) gi1 = (x1 @ [Wih_l1f;Wih_l1b]^T + bias) * colscale  (masked blocks skipped)
    gemm192_kernel<<<(Bb * Tt) / 64, 256>>>(p_x1, Wih_l1f, Wih_l1b, bih_l1f, bih_l1b,
                                            p_gi1, Bb * Tt, 64, mask);
    // 5) layer-1 recurrence -> final hiddens
    gru_kernel<false><<<128, 128>>>(p_gi1, nullptr, Whh_l1f, bhh_l1f, Whh_l1b, bhh_l1b);
    // 6) output projection
    out_kernel<<<8, 1024>>>(Wout, bout, out);
}